// round 8
// baseline (speedup 1.0000x reference)
#include <cuda_runtime.h>
#include <cstdio>
#include <unistd.h>

#define NPTS 80
#define PITCH 81
#define NDELAYS 32
#define NPARAMS 256
#define IMG 6400
#define LAMBDA 0.03f
#define X_FLOATS (NDELAYS*IMG)          // 204800 floats for best_x
#define TF_REAL  (NDELAYS*IMG)          // 204800 floats for best tf (real-valued)
#define OUT_FLOATS (X_FLOATS + TF_REAL + 4)      // 409604
#define TF_TOTAL ((long long)NPARAMS * NDELAYS * IMG)   // 52428800 floats

// ---------------- workspace ----------------
__device__ float2 g_Yf[NDELAYS * IMG];
__device__ float  g_partial[NPARAMS * NDELAYS];
__device__ int    g_best;

__device__ __forceinline__ float gld(const float* p, long long i, long long imax) {
    return (p != nullptr && i >= 0 && i <= imax) ? p[i] : 0.f;
}

// ---------------- 16-point FFT in registers (U=+1 inverse, U=-1 forward, unscaled) ----------------
template<int U>
__device__ __forceinline__ void fft16r(float2* v) {
    const float C16[8] = {1.f, 0.9238795325112867f, 0.7071067811865476f, 0.3826834323650898f,
                          0.f, -0.3826834323650898f, -0.7071067811865476f, -0.9238795325112867f};
    const float S16[8] = {0.f, 0.3826834323650898f, 0.7071067811865476f, 0.9238795325112867f,
                          1.f, 0.9238795325112867f, 0.7071067811865476f, 0.3826834323650898f};
    float2 t;
    t = v[1];  v[1]  = v[8];  v[8]  = t;
    t = v[2];  v[2]  = v[4];  v[4]  = t;
    t = v[3];  v[3]  = v[12]; v[12] = t;
    t = v[5];  v[5]  = v[10]; v[10] = t;
    t = v[7];  v[7]  = v[14]; v[14] = t;
    t = v[11]; v[11] = v[13]; v[13] = t;
#pragma unroll
    for (int len = 2; len <= 16; len <<= 1) {
        const int half = len >> 1;
        const int step = 16 / len;
#pragma unroll
        for (int i = 0; i < 16; i += len) {
#pragma unroll
            for (int j = 0; j < half; j++) {
                float wc = C16[j * step];
                float ws = (float)U * S16[j * step];
                float2 a = v[i + j], b = v[i + j + half];
                float tr = b.x * wc - b.y * ws;
                float ti = b.x * ws + b.y * wc;
                v[i + j]        = make_float2(a.x + tr, a.y + ti);
                v[i + j + half] = make_float2(a.x - tr, a.y - ti);
            }
        }
    }
}

// ---------------- 80x80 2D FFT (unscaled), in place on X, T scratch ----------------
template<int U>
__device__ void fft2d80(float2* X, float2* T, const float2* w80, int tid) {
    const float C5[5] = {1.f, 0.30901699437494745f, -0.8090169943749475f,
                         -0.8090169943749475f, 0.30901699437494745f};
    const float S5[5] = {0.f, 0.9510565162951535f, 0.5877852522924731f,
                         -0.5877852522924731f, -0.9510565162951535f};
    for (int pass = 0; pass < 2; ++pass) {
        if (tid < NPTS) {
            const float2* s = X + tid * PITCH;
            float2* trow = T + tid * PITCH;
#pragma unroll
            for (int n2 = 0; n2 < 16; n2++) {
                float2 c[5];
#pragma unroll
                for (int n1 = 0; n1 < 5; n1++) c[n1] = s[16 * n1 + n2];
#pragma unroll
                for (int k = 0; k < 5; k++) {
                    float re = c[0].x, im = c[0].y;
#pragma unroll
                    for (int n = 1; n < 5; n++) {
                        int m = (n * k) % 5;
                        float wc = C5[m], ws = (float)U * S5[m];
                        re += c[n].x * wc - c[n].y * ws;
                        im += c[n].x * ws + c[n].y * wc;
                    }
                    float2 dv = make_float2(re, im);
                    if (k > 0) {
                        float wc = w80[n2 * k].x, ws = (float)U * w80[n2 * k].y;
                        dv = make_float2(dv.x * wc - dv.y * ws, dv.x * ws + dv.y * wc);
                    }
                    trow[k * 16 + n2] = dv;
                }
            }
        }
        __syncthreads();
        if (tid < NPTS) {
            const float2* trow = T + tid * PITCH;
#pragma unroll
            for (int k1 = 0; k1 < 5; k1++) {
                float2 v[16];
#pragma unroll
                for (int n2 = 0; n2 < 16; n2++) v[n2] = trow[k1 * 16 + n2];
                fft16r<U>(v);
#pragma unroll
                for (int k2 = 0; k2 < 16; k2++) X[(k1 + 5 * k2) * PITCH + tid] = v[k2];
            }
        }
        __syncthreads();
    }
}

// ---------------- deterministic block reduce ----------------
__device__ float blockReduceSum(float v, float* red, int tid) {
#pragma unroll
    for (int o = 16; o > 0; o >>= 1) v += __shfl_down_sync(0xffffffffu, v, o);
    if ((tid & 31) == 0) red[tid >> 5] = v;
    __syncthreads();
    if (tid == 0) {
        float s = 0.f;
        int nw = blockDim.x >> 5;
        for (int w = 0; w < nw; w++) s += red[w];
        red[0] = s;
    }
    __syncthreads();
    float r = red[0];
    __syncthreads();
    return r;
}

#define SMEM_F2 (2 * NPTS * PITCH + 80)
#define SMEM_BYTES (SMEM_F2 * sizeof(float2) + 64 * sizeof(float))

__device__ __forceinline__ void fill_w80(float2* w80, int tid) {
    if (tid < 80) {
        float sv, cv;
        sincospif((float)tid * (1.0f / 40.0f), &sv, &cv);   // 2*pi*tid/80
        w80[tid] = make_float2(cv, sv);
    }
}

// ---------------- kernel 1: Yf = fft2(y), 32 blocks ----------------
__global__ void yf_kernel(const float* __restrict__ y) {
    extern __shared__ float sm[];
    float2* A = (float2*)sm;
    float2* B = A + NPTS * PITCH;
    float2* w80 = B + NPTS * PITCH;
    int tid = threadIdx.x;
    int d = blockIdx.x;
    fill_w80(w80, tid);
    for (int idx = tid; idx < IMG; idx += blockDim.x)
        A[(idx / 80) * PITCH + (idx % 80)] = make_float2(gld(y, (long long)d * IMG + idx, X_FLOATS - 1), 0.f);
    __syncthreads();
    fft2d80<-1>(A, B, w80, tid);
    for (int idx = tid; idx < IMG; idx += blockDim.x)
        g_Yf[d * IMG + idx] = A[(idx / 80) * PITCH + (idx % 80)];
}

// ---------------- kernel 2: per-(p,d) partial loss, 8192 blocks (TF is REAL float32) ----------------
__global__ void loss_kernel(const float* __restrict__ tf, const float* __restrict__ y) {
    extern __shared__ float sm[];
    float2* A = (float2*)sm;
    float2* B = A + NPTS * PITCH;
    float2* w80 = B + NPTS * PITCH;
    float* red = (float*)(w80 + 80);
    int tid = threadIdx.x;
    int pd = blockIdx.x;
    int d = pd & 31;
    fill_w80(w80, tid);
    long long base = (long long)pd * IMG;
    for (int idx = tid; idx < IMG; idx += blockDim.x)
        A[(idx / 80) * PITCH + (idx % 80)] = make_float2(gld(tf, base + idx, TF_TOTAL - 1), 0.f);
    __syncthreads();
    fft2d80<1>(A, B, w80, tid);          // unscaled ifft2(TF); 1/6400 cancels in normalization
    float s = 0.f;
    for (int idx = tid; idx < IMG; idx += blockDim.x) {
        float2 v = A[(idx / 80) * PITCH + (idx % 80)];
        s += sqrtf(v.x * v.x + v.y * v.y);
    }
    float S = blockReduceSum(s, red, tid);
    float invS = 1.0f / S;
    const float2* yf = g_Yf + d * IMG;
    for (int idx = tid; idx < IMG; idx += blockDim.x) {
        int i = idx / 80, j = idx % 80;
        int si = (i >= 40) ? i - 40 : i + 40;
        int sj = (j >= 40) ? j - 40 : j + 40;
        float2 a = A[si * PITCH + sj];
        float m = sqrtf(a.x * a.x + a.y * a.y) * invS;   // psf (shifted, normalized)
        float2 f = yf[idx];
        B[i * PITCH + j] = make_float2(m * f.x, m * f.y);
    }
    __syncthreads();
    fft2d80<1>(B, A, w80, tid);          // unscaled ifft2(psf * Yf)
    float acc = 0.f;
    for (int idx = tid; idx < IMG; idx += blockDim.x) {
        int i = idx / 80, j = idx % 80;
        int si = (i >= 40) ? i - 40 : i + 40;
        int sj = (j >= 40) ? j - 40 : j + 40;
        float2 v = B[si * PITCH + sj];
        float yh = sqrtf(v.x * v.x + v.y * v.y) * (1.0f / 6400.0f);
        float df = gld(y, (long long)d * IMG + idx, X_FLOATS - 1) - yh;
        acc += df * df;
    }
    float tot = blockReduceSum(acc, red, tid);
    if (tid == 0) g_partial[pd] = tot;
}

// ---------------- kernel 3: reduce + argmin ----------------
__global__ void argmin_kernel(const float* __restrict__ params, float* __restrict__ out) {
    __shared__ float sl[NPARAMS];
    __shared__ int   si[NPARAMS];
    int tid = threadIdx.x;
    float s = 0.f;
    for (int d = 0; d < NDELAYS; d++) s += g_partial[tid * NDELAYS + d];
    float loss = s / (float)(NDELAYS * IMG);
    sl[tid] = loss; si[tid] = tid;
    __syncthreads();
    for (int st = 128; st > 0; st >>= 1) {
        if (tid < st) {
            float lo = sl[tid + st];
            if (lo < sl[tid] || (lo == sl[tid] && si[tid + st] < si[tid])) {
                sl[tid] = lo; si[tid] = si[tid + st];
            }
        }
        __syncthreads();
    }
    if (tid == 0) {
        g_best = si[0];
        out[X_FLOATS + TF_REAL + 0] = gld(params, (long long)si[0] * 3 + 0, 767);
        out[X_FLOATS + TF_REAL + 1] = gld(params, (long long)si[0] * 3 + 1, 767);
        out[X_FLOATS + TF_REAL + 2] = gld(params, (long long)si[0] * 3 + 2, 767);
        out[X_FLOATS + TF_REAL + 3] = sl[0];
    }
}

// ---------------- kernel 4: copy best TF (real floats) ----------------
__global__ void copytf_kernel(const float* __restrict__ tf, float* __restrict__ out) {
    long long base = (long long)g_best * TF_REAL;
    for (int i = blockIdx.x * blockDim.x + threadIdx.x; i < TF_REAL; i += gridDim.x * blockDim.x)
        out[X_FLOATS + i] = gld(tf, base + i, TF_TOTAL - 1);
}

// ---------------- kernel 5: best_x (Wiener deconv for winner), 32 blocks ----------------
__global__ void bestx_kernel(const float* __restrict__ tf, float* __restrict__ out) {
    extern __shared__ float sm[];
    float2* A = (float2*)sm;
    float2* B = A + NPTS * PITCH;
    float2* w80 = B + NPTS * PITCH;
    float* red = (float*)(w80 + 80);
    int tid = threadIdx.x;
    int d = blockIdx.x;
    fill_w80(w80, tid);
    long long base = ((long long)g_best * NDELAYS + d) * IMG;
    for (int idx = tid; idx < IMG; idx += blockDim.x)
        A[(idx / 80) * PITCH + (idx % 80)] = make_float2(gld(tf, base + idx, TF_TOTAL - 1), 0.f);
    __syncthreads();
    fft2d80<1>(A, B, w80, tid);
    float s = 0.f;
    for (int idx = tid; idx < IMG; idx += blockDim.x) {
        float2 v = A[(idx / 80) * PITCH + (idx % 80)];
        s += sqrtf(v.x * v.x + v.y * v.y);
    }
    float S = blockReduceSum(s, red, tid);
    float invS = 1.0f / S;
    for (int idx = tid; idx < IMG; idx += blockDim.x) {
        int i = idx / 80, j = idx % 80;
        int si = (i >= 40) ? i - 40 : i + 40;
        int sj = (j >= 40) ? j - 40 : j + 40;
        float2 a = A[si * PITCH + sj];
        B[i * PITCH + j] = make_float2(sqrtf(a.x * a.x + a.y * a.y) * invS, 0.f);
    }
    __syncthreads();
    fft2d80<-1>(B, A, w80, tid);         // H = fft2(psf)
    const float2* yf = g_Yf + d * IMG;
    for (int idx = tid; idx < IMG; idx += blockDim.x) {
        int i = idx / 80, j = idx % 80;
        float2 h = B[i * PITCH + j];
        float2 f = yf[idx];
        float den = h.x * h.x + h.y * h.y + LAMBDA;
        B[i * PITCH + j] = make_float2((h.x * f.x + h.y * f.y) / den,
                                       (h.x * f.y - h.y * f.x) / den);
    }
    __syncthreads();
    fft2d80<1>(B, A, w80, tid);
    for (int idx = tid; idx < IMG; idx += blockDim.x) {
        int i = idx / 80, j = idx % 80;
        int si = (i >= 40) ? i - 40 : i + 40;
        int sj = (j >= 40) ? j - 40 : j + 40;
        float2 v = B[si * PITCH + sj];
        out[d * IMG + idx] = sqrtf(v.x * v.x + v.y * v.y) * (1.0f / 6400.0f);
    }
}

// ---------------- host helpers ----------------
static bool is_capturing() {
    cudaStreamCaptureStatus st = cudaStreamCaptureStatusNone;
    cudaStreamIsCapturing(0, &st);
    cudaGetLastError();
    return st != cudaStreamCaptureStatusNone;
}

static void diag_stage(const char* name, bool capturing) {
    if (capturing) return;
    usleep(100000);
    cudaError_t q = cudaStreamQuery(0);
    if (q == cudaErrorNotReady) { usleep(300000); q = cudaStreamQuery(0); }
    fprintf(stderr, "[diag] stage %-8s query=%d (%s)\n", name, (int)q, cudaGetErrorName(q));
    fflush(stderr);
}

// ---------------- launcher ----------------
extern "C" void kernel_launch(void* const* d_in, const int* in_sizes, int n_in,
                              void* d_out, int out_size) {
    if (n_in < 3 || d_in == nullptr || d_out == nullptr) return;
    bool capturing = is_capturing();

    const float* y      = (const float*)d_in[0];   // 204800 floats
    const float* tf     = (const float*)d_in[1];   // 52428800 floats (TF is real: cos(k(d-w)))
    const float* params = (const float*)d_in[2];   // 768 floats
    float* out = (float*)d_out;                    // 409604 floats: [x | tf | params | loss]

    if (!capturing) {
        fprintf(stderr, "[diag] n_in=%d sizes={%d,%d,%d} out_size=%d\n",
                n_in, in_sizes[0], in_sizes[1], in_sizes[2], out_size);
        fflush(stderr);
    }

    cudaFuncSetAttribute(yf_kernel,    cudaFuncAttributeMaxDynamicSharedMemorySize, (int)SMEM_BYTES);
    cudaFuncSetAttribute(loss_kernel,  cudaFuncAttributeMaxDynamicSharedMemorySize, (int)SMEM_BYTES);
    cudaFuncSetAttribute(bestx_kernel, cudaFuncAttributeMaxDynamicSharedMemorySize, (int)SMEM_BYTES);

    yf_kernel<<<NDELAYS, 128, SMEM_BYTES>>>(y);
    diag_stage("yf", capturing);
    loss_kernel<<<NPARAMS * NDELAYS, 128, SMEM_BYTES>>>(tf, y);
    diag_stage("loss", capturing);
    argmin_kernel<<<1, NPARAMS>>>(params, out);
    copytf_kernel<<<256, 256>>>(tf, out);
    bestx_kernel<<<NDELAYS, 128, SMEM_BYTES>>>(tf, out);
    diag_stage("tail", capturing);
}

// round 9
// speedup vs baseline: 1.1857x; 1.1857x over previous
#include <cuda_runtime.h>

#define NPTS 80
#define PITCH 81
#define NDELAYS 32
#define NPARAMS 256
#define IMG 6400
#define LAMBDA 0.03f
#define X_FLOATS (NDELAYS*IMG)          // 204800 floats for best_x
#define TF_REAL  (NDELAYS*IMG)          // 204800 floats for best tf (real-valued)
#define TF_TOTAL ((long long)NPARAMS * NDELAYS * IMG)   // 52428800 floats
#define NTHR 320                        // 4 threads per row

// ---------------- workspace ----------------
__device__ float2 g_Yf[NDELAYS * IMG];
__device__ float  g_partial[NPARAMS * NDELAYS];
__device__ int    g_best;

__device__ __forceinline__ float gld(const float* p, long long i, long long imax) {
    return (i >= 0 && i <= imax) ? p[i] : 0.f;
}

// ---------------- 16-point FFT in registers (U=+1 inverse, U=-1 forward, unscaled) ----------------
template<int U>
__device__ __forceinline__ void fft16r(float2* v) {
    const float C16[8] = {1.f, 0.9238795325112867f, 0.7071067811865476f, 0.3826834323650898f,
                          0.f, -0.3826834323650898f, -0.7071067811865476f, -0.9238795325112867f};
    const float S16[8] = {0.f, 0.3826834323650898f, 0.7071067811865476f, 0.9238795325112867f,
                          1.f, 0.9238795325112867f, 0.7071067811865476f, 0.3826834323650898f};
    float2 t;
    t = v[1];  v[1]  = v[8];  v[8]  = t;
    t = v[2];  v[2]  = v[4];  v[4]  = t;
    t = v[3];  v[3]  = v[12]; v[12] = t;
    t = v[5];  v[5]  = v[10]; v[10] = t;
    t = v[7];  v[7]  = v[14]; v[14] = t;
    t = v[11]; v[11] = v[13]; v[13] = t;
#pragma unroll
    for (int len = 2; len <= 16; len <<= 1) {
        const int half = len >> 1;
        const int step = 16 / len;
#pragma unroll
        for (int i = 0; i < 16; i += len) {
#pragma unroll
            for (int j = 0; j < half; j++) {
                float wc = C16[j * step];
                float ws = (float)U * S16[j * step];
                float2 a = v[i + j], b = v[i + j + half];
                float tr = b.x * wc - b.y * ws;
                float ti = b.x * ws + b.y * wc;
                v[i + j]        = make_float2(a.x + tr, a.y + ti);
                v[i + j + half] = make_float2(a.x - tr, a.y - ti);
            }
        }
    }
}

// ---------------- 80x80 2D FFT, 4 threads per row (320 threads), in place on X, T scratch ----------------
template<int U>
__device__ void fft2d80(float2* X, float2* T, const float2* w80, int tid) {
    const float C5[5] = {1.f, 0.30901699437494745f, -0.8090169943749475f,
                         -0.8090169943749475f, 0.30901699437494745f};
    const float S5[5] = {0.f, 0.9510565162951535f, 0.5877852522924731f,
                         -0.5877852522924731f, -0.9510565162951535f};
    const int row = tid >> 2;       // 0..79
    const int j   = tid & 3;        // 0..3
#pragma unroll
    for (int pass = 0; pass < 2; ++pass) {
        // stage 1: radix-5 DFT + W80 twiddle over 4 of the 16 n2-columns
        {
            const float2* s = X + row * PITCH;
            float2* trow = T + row * PITCH;
#pragma unroll
            for (int m = 0; m < 4; m++) {
                const int n2 = j + 4 * m;
                float2 c[5];
#pragma unroll
                for (int n1 = 0; n1 < 5; n1++) c[n1] = s[16 * n1 + n2];
#pragma unroll
                for (int k = 0; k < 5; k++) {
                    float re = c[0].x, im = c[0].y;
#pragma unroll
                    for (int n = 1; n < 5; n++) {
                        int mm = (n * k) % 5;
                        float wc = C5[mm], ws = (float)U * S5[mm];
                        re += c[n].x * wc - c[n].y * ws;
                        im += c[n].x * ws + c[n].y * wc;
                    }
                    float2 dv = make_float2(re, im);
                    if (k > 0) {
                        float wc = w80[n2 * k].x, ws = (float)U * w80[n2 * k].y;
                        dv = make_float2(dv.x * wc - dv.y * ws, dv.x * ws + dv.y * wc);
                    }
                    trow[k * 16 + n2] = dv;
                }
            }
        }
        __syncthreads();
        // stage 2: radix-16 FFTs; j=0,1,2 do k1=j, j=3 does k1=3,4
        {
            const float2* trow = T + row * PITCH;
            const int nk = (j == 3) ? 2 : 1;
#pragma unroll
            for (int q = 0; q < 2; q++) {
                if (q >= nk) break;
                const int k1 = (j == 3) ? (3 + q) : j;
                float2 v[16];
#pragma unroll
                for (int n2 = 0; n2 < 16; n2++) v[n2] = trow[k1 * 16 + n2];
                fft16r<U>(v);
#pragma unroll
                for (int k2 = 0; k2 < 16; k2++) X[(k1 + 5 * k2) * PITCH + row] = v[k2];
            }
        }
        __syncthreads();
    }
}

// ---------------- deterministic block reduce (blockDim = NTHR = 10 warps) ----------------
__device__ float blockReduceSum(float v, float* red, int tid) {
#pragma unroll
    for (int o = 16; o > 0; o >>= 1) v += __shfl_down_sync(0xffffffffu, v, o);
    if ((tid & 31) == 0) red[tid >> 5] = v;
    __syncthreads();
    if (tid == 0) {
        float s = 0.f;
        for (int w = 0; w < NTHR / 32; w++) s += red[w];
        red[0] = s;
    }
    __syncthreads();
    float r = red[0];
    __syncthreads();
    return r;
}

#define SMEM_F2 (2 * NPTS * PITCH + 80)
#define SMEM_BYTES (SMEM_F2 * sizeof(float2) + 64 * sizeof(float))

__device__ __forceinline__ void fill_w80(float2* w80, int tid) {
    if (tid < 80) {
        float sv, cv;
        sincospif((float)tid * (1.0f / 40.0f), &sv, &cv);   // 2*pi*tid/80
        w80[tid] = make_float2(cv, sv);
    }
}

// ---------------- kernel 1: Yf = fft2(y), 32 blocks ----------------
__global__ void yf_kernel(const float* __restrict__ y) {
    extern __shared__ float sm[];
    float2* A = (float2*)sm;
    float2* B = A + NPTS * PITCH;
    float2* w80 = B + NPTS * PITCH;
    int tid = threadIdx.x;
    int d = blockIdx.x;
    fill_w80(w80, tid);
    for (int idx = tid; idx < IMG; idx += NTHR)
        A[(idx / 80) * PITCH + (idx % 80)] = make_float2(gld(y, (long long)d * IMG + idx, X_FLOATS - 1), 0.f);
    __syncthreads();
    fft2d80<-1>(A, B, w80, tid);
    for (int idx = tid; idx < IMG; idx += NTHR)
        g_Yf[d * IMG + idx] = A[(idx / 80) * PITCH + (idx % 80)];
}

// ---------------- kernel 2: per-(p,d) partial loss, 8192 blocks (TF is REAL float32) ----------------
__global__ void __launch_bounds__(NTHR, 2) loss_kernel(const float* __restrict__ tf, const float* __restrict__ y) {
    extern __shared__ float sm[];
    float2* A = (float2*)sm;
    float2* B = A + NPTS * PITCH;
    float2* w80 = B + NPTS * PITCH;
    float* red = (float*)(w80 + 80);
    int tid = threadIdx.x;
    int pd = blockIdx.x;
    int d = pd & 31;
    fill_w80(w80, tid);
    long long base = (long long)pd * IMG;
    for (int idx = tid; idx < IMG; idx += NTHR)
        A[(idx / 80) * PITCH + (idx % 80)] = make_float2(gld(tf, base + idx, TF_TOTAL - 1), 0.f);
    __syncthreads();
    fft2d80<1>(A, B, w80, tid);          // unscaled ifft2(TF); 1/6400 cancels in normalization
    float s = 0.f;
    for (int idx = tid; idx < IMG; idx += NTHR) {
        float2 v = A[(idx / 80) * PITCH + (idx % 80)];
        s += sqrtf(v.x * v.x + v.y * v.y);
    }
    float S = blockReduceSum(s, red, tid);
    float invS = 1.0f / S;
    const float2* yf = g_Yf + d * IMG;
    for (int idx = tid; idx < IMG; idx += NTHR) {
        int i = idx / 80, j = idx % 80;
        int si = (i >= 40) ? i - 40 : i + 40;
        int sj = (j >= 40) ? j - 40 : j + 40;
        float2 a = A[si * PITCH + sj];
        float m = sqrtf(a.x * a.x + a.y * a.y) * invS;   // psf (shifted, normalized)
        float2 f = yf[idx];
        B[i * PITCH + j] = make_float2(m * f.x, m * f.y);
    }
    __syncthreads();
    fft2d80<1>(B, A, w80, tid);          // unscaled ifft2(psf * Yf)
    float acc = 0.f;
    for (int idx = tid; idx < IMG; idx += NTHR) {
        int i = idx / 80, j = idx % 80;
        int si = (i >= 40) ? i - 40 : i + 40;
        int sj = (j >= 40) ? j - 40 : j + 40;
        float2 v = B[si * PITCH + sj];
        float yh = sqrtf(v.x * v.x + v.y * v.y) * (1.0f / 6400.0f);
        float df = gld(y, (long long)d * IMG + idx, X_FLOATS - 1) - yh;
        acc += df * df;
    }
    float tot = blockReduceSum(acc, red, tid);
    if (tid == 0) g_partial[pd] = tot;
}

// ---------------- kernel 3: reduce + argmin ----------------
__global__ void argmin_kernel(const float* __restrict__ params, float* __restrict__ out) {
    __shared__ float sl[NPARAMS];
    __shared__ int   si[NPARAMS];
    int tid = threadIdx.x;
    float s = 0.f;
    for (int d = 0; d < NDELAYS; d++) s += g_partial[tid * NDELAYS + d];
    float loss = s / (float)(NDELAYS * IMG);
    sl[tid] = loss; si[tid] = tid;
    __syncthreads();
    for (int st = 128; st > 0; st >>= 1) {
        if (tid < st) {
            float lo = sl[tid + st];
            if (lo < sl[tid] || (lo == sl[tid] && si[tid + st] < si[tid])) {
                sl[tid] = lo; si[tid] = si[tid + st];
            }
        }
        __syncthreads();
    }
    if (tid == 0) {
        g_best = si[0];
        out[X_FLOATS + TF_REAL + 0] = gld(params, (long long)si[0] * 3 + 0, 767);
        out[X_FLOATS + TF_REAL + 1] = gld(params, (long long)si[0] * 3 + 1, 767);
        out[X_FLOATS + TF_REAL + 2] = gld(params, (long long)si[0] * 3 + 2, 767);
        out[X_FLOATS + TF_REAL + 3] = sl[0];
    }
}

// ---------------- kernel 4: copy best TF (real floats) ----------------
__global__ void copytf_kernel(const float* __restrict__ tf, float* __restrict__ out) {
    long long base = (long long)g_best * TF_REAL;
    for (int i = blockIdx.x * blockDim.x + threadIdx.x; i < TF_REAL; i += gridDim.x * blockDim.x)
        out[X_FLOATS + i] = gld(tf, base + i, TF_TOTAL - 1);
}

// ---------------- kernel 5: best_x (Wiener deconv for winner), 32 blocks ----------------
__global__ void bestx_kernel(const float* __restrict__ tf, float* __restrict__ out) {
    extern __shared__ float sm[];
    float2* A = (float2*)sm;
    float2* B = A + NPTS * PITCH;
    float2* w80 = B + NPTS * PITCH;
    float* red = (float*)(w80 + 80);
    int tid = threadIdx.x;
    int d = blockIdx.x;
    fill_w80(w80, tid);
    long long base = ((long long)g_best * NDELAYS + d) * IMG;
    for (int idx = tid; idx < IMG; idx += NTHR)
        A[(idx / 80) * PITCH + (idx % 80)] = make_float2(gld(tf, base + idx, TF_TOTAL - 1), 0.f);
    __syncthreads();
    fft2d80<1>(A, B, w80, tid);
    float s = 0.f;
    for (int idx = tid; idx < IMG; idx += NTHR) {
        float2 v = A[(idx / 80) * PITCH + (idx % 80)];
        s += sqrtf(v.x * v.x + v.y * v.y);
    }
    float S = blockReduceSum(s, red, tid);
    float invS = 1.0f / S;
    for (int idx = tid; idx < IMG; idx += NTHR) {
        int i = idx / 80, j = idx % 80;
        int si = (i >= 40) ? i - 40 : i + 40;
        int sj = (j >= 40) ? j - 40 : j + 40;
        float2 a = A[si * PITCH + sj];
        B[i * PITCH + j] = make_float2(sqrtf(a.x * a.x + a.y * a.y) * invS, 0.f);
    }
    __syncthreads();
    fft2d80<-1>(B, A, w80, tid);         // H = fft2(psf)
    const float2* yf = g_Yf + d * IMG;
    for (int idx = tid; idx < IMG; idx += NTHR) {
        int i = idx / 80, j = idx % 80;
        float2 h = B[i * PITCH + j];
        float2 f = yf[idx];
        float den = h.x * h.x + h.y * h.y + LAMBDA;
        B[i * PITCH + j] = make_float2((h.x * f.x + h.y * f.y) / den,
                                       (h.x * f.y - h.y * f.x) / den);
    }
    __syncthreads();
    fft2d80<1>(B, A, w80, tid);
    for (int idx = tid; idx < IMG; idx += NTHR) {
        int i = idx / 80, j = idx % 80;
        int si = (i >= 40) ? i - 40 : i + 40;
        int sj = (j >= 40) ? j - 40 : j + 40;
        float2 v = B[si * PITCH + sj];
        out[d * IMG + idx] = sqrtf(v.x * v.x + v.y * v.y) * (1.0f / 6400.0f);
    }
}

// ---------------- launcher ----------------
extern "C" void kernel_launch(void* const* d_in, const int* in_sizes, int n_in,
                              void* d_out, int out_size) {
    (void)in_sizes; (void)out_size;
    if (n_in < 3 || d_in == nullptr || d_out == nullptr) return;

    const float* y      = (const float*)d_in[0];   // 204800 floats
    const float* tf     = (const float*)d_in[1];   // 52428800 floats (TF real: cos(k(d-w)))
    const float* params = (const float*)d_in[2];   // 768 floats
    float* out = (float*)d_out;                    // 409604 floats: [x | tf | params | loss]

    cudaFuncSetAttribute(yf_kernel,    cudaFuncAttributeMaxDynamicSharedMemorySize, (int)SMEM_BYTES);
    cudaFuncSetAttribute(loss_kernel,  cudaFuncAttributeMaxDynamicSharedMemorySize, (int)SMEM_BYTES);
    cudaFuncSetAttribute(bestx_kernel, cudaFuncAttributeMaxDynamicSharedMemorySize, (int)SMEM_BYTES);

    yf_kernel<<<NDELAYS, NTHR, SMEM_BYTES>>>(y);
    loss_kernel<<<NPARAMS * NDELAYS, NTHR, SMEM_BYTES>>>(tf, y);
    argmin_kernel<<<1, NPARAMS>>>(params, out);
    copytf_kernel<<<256, 256>>>(tf, out);
    bestx_kernel<<<NDELAYS, NTHR, SMEM_BYTES>>>(tf, out);
}